// round 7
// baseline (speedup 1.0000x reference)
#include <cuda_runtime.h>

#define BSZ   4
#define CH    128
#define HID   256
#define OUTD  64
#define EPSV  1e-5f
#define ALLM  0xffffffffu
#define RSTR  264              // r_s row stride (floats): banks (q*8+j)%32 distinct

// ---------------------------------------------------------------------------
// Grid 20 = 5 levels x 4 batches. Block 1024. No inter-block traffic.
//   Each block redundantly computes phase1 for its level (all 256 units),
//   then phase2 for ITS batch only, with all 1024 threads (16 lanes/output).
// ---------------------------------------------------------------------------
__global__ __launch_bounds__(1024, 1)
void proj_fused_kernel(const float* __restrict__ x0,
                       const float* __restrict__ x1,
                       const float* __restrict__ x2,
                       const float* __restrict__ x3,
                       const float* __restrict__ x4,
                       const int*   __restrict__ p,
                       const float* __restrict__ w1,
                       const float* __restrict__ b1,
                       const float* __restrict__ gamma,
                       const float* __restrict__ beta,
                       const float* __restrict__ w2,
                       const float* __restrict__ b2,
                       float*       __restrict__ out)
{
    const int k    = blockIdx.x >> 2;   // level 0..4
    const int bsel = blockIdx.x & 3;    // batch this block outputs
    const int t    = threadIdx.x;       // 0..1023

    __shared__ float f_s[BSZ][CH];      // gathered features
    __shared__ float r_s[BSZ * RSTR];   // post-ReLU hidden, padded rows

    const int j = t >> 2;               // hidden unit 0..255
    const int q = t & 3;                // channel quarter

    // ---- prefetch w1 (interleaved slots: coalesced, 8 lines per warp-LDG) ----
    const float4* wrow = (const float4*)(w1 + ((long long)k * HID + j) * CH);
    float4 wv[8];
    #pragma unroll
    for (int i = 0; i < 8; ++i)
        wv[i] = wrow[q + 4 * i];

    const float bias = b1[k * HID + j];
    const float gam  = gamma[k * HID + j];
    const float bet  = beta[k * HID + j];

    // phase2 assignment (declared early; w2 prefetch happens later)
    const int o  = t >> 4;              // output 0..63
    const int s2 = t & 15;              // 16-lane slice
    const float bias2 = b2[k * OUTD + o];

    // ---- gather 512 scattered floats (threads 0..511) ----
    const float* xs;
    switch (k) {
        case 0: xs = x0; break;
        case 1: xs = x1; break;
        case 2: xs = x2; break;
        case 3: xs = x3; break;
        default: xs = x4; break;
    }
    const int shift = k + 1;
    const int side  = 128 >> shift;

    if (t < BSZ * CH) {
        const int b = t >> 7;
        const int c = t & (CH - 1);
        const int q0 = p[b * 3 + 0] >> shift;
        const int q1 = p[b * 3 + 1] >> shift;
        const int q2 = p[b * 3 + 2] >> shift;
        const long long idx =
            ((((long long)(b * CH + c) * side + q0) * side + q1) * side + q2);
        f_s[b][c] = xs[idx];
    }
    __syncthreads();

    // ---- phase1: 8 interleaved float4 x 4 batches (32 MACs/thread) ----
    const float4* f0 = (const float4*)f_s[0];
    const float4* f1 = (const float4*)f_s[1];
    const float4* f2 = (const float4*)f_s[2];
    const float4* f3 = (const float4*)f_s[3];

    float a0 = 0.f, a1 = 0.f, a2 = 0.f, a3 = 0.f;
    #pragma unroll
    for (int i = 0; i < 8; ++i) {
        const int fi = q + 4 * i;
        const float4 w = wv[i];
        float4 v;
        v = f0[fi]; a0 += v.x*w.x + v.y*w.y + v.z*w.z + v.w*w.w;
        v = f1[fi]; a1 += v.x*w.x + v.y*w.y + v.z*w.z + v.w*w.w;
        v = f2[fi]; a2 += v.x*w.x + v.y*w.y + v.z*w.z + v.w*w.w;
        v = f3[fi]; a3 += v.x*w.x + v.y*w.y + v.z*w.z + v.w*w.w;
    }
    #pragma unroll
    for (int m = 1; m < 4; m <<= 1) {
        a0 += __shfl_xor_sync(ALLM, a0, m);
        a1 += __shfl_xor_sync(ALLM, a1, m);
        a2 += __shfl_xor_sync(ALLM, a2, m);
        a3 += __shfl_xor_sync(ALLM, a3, m);
    }

    // ---- BN + ReLU; lane q writes batch b=q (conflict-free with RSTR) ----
    a0 += bias; a1 += bias; a2 += bias; a3 += bias;
    const float mean = 0.25f * (a0 + a1 + a2 + a3);
    const float d0 = a0 - mean, d1 = a1 - mean, d2 = a2 - mean, d3 = a3 - mean;
    const float var = 0.25f * (d0*d0 + d1*d1 + d2*d2 + d3*d3);
    const float scl = gam * rsqrtf(var + EPSV);

    const float d = (q == 0) ? d0 : (q == 1) ? d1 : (q == 2) ? d2 : d3;
    r_s[q * RSTR + j] = fmaxf(d * scl + bet, 0.f);

    // ---- prefetch w2 slice into regs (independent of r_s; hides under BAR) ----
    const float4* w2row = (const float4*)(w2 + ((long long)k * OUTD + o) * HID);
    float4 wv2[4];
    #pragma unroll
    for (int i = 0; i < 4; ++i)
        wv2[i] = w2row[s2 + 16 * i];

    __syncthreads();

    // ---- phase2: this block's batch only; 16 lanes per output ----
    const float4* r4 = (const float4*)(r_s + bsel * RSTR);
    float acc = 0.f;
    #pragma unroll
    for (int i = 0; i < 4; ++i) {
        const float4 w = wv2[i];
        const float4 r = r4[s2 + 16 * i];
        acc += r.x*w.x + r.y*w.y + r.z*w.z + r.w*w.w;
    }
    #pragma unroll
    for (int m = 1; m < 16; m <<= 1)
        acc += __shfl_xor_sync(ALLM, acc, m);

    if (s2 == 0)
        out[k * (BSZ * OUTD) + bsel * OUTD + o] = acc + bias2;
}

extern "C" void kernel_launch(void* const* d_in, const int* in_sizes, int n_in,
                              void* d_out, int out_size)
{
    (void)in_sizes; (void)n_in; (void)out_size;
    const float* x0    = (const float*)d_in[0];
    const float* x1    = (const float*)d_in[1];
    const float* x2    = (const float*)d_in[2];
    const float* x3    = (const float*)d_in[3];
    const float* x4    = (const float*)d_in[4];
    const int*   p     = (const int*)  d_in[5];
    const float* w1    = (const float*)d_in[6];
    const float* b1    = (const float*)d_in[7];
    const float* gamma = (const float*)d_in[8];
    const float* beta  = (const float*)d_in[9];
    const float* w2    = (const float*)d_in[10];
    const float* b2v   = (const float*)d_in[11];
    float* out = (float*)d_out;

    proj_fused_kernel<<<20, 1024>>>(x0, x1, x2, x3, x4, p,
                                    w1, b1, gamma, beta, w2, b2v, out);
}

// round 8
// speedup vs baseline: 1.2694x; 1.2694x over previous
#include <cuda_runtime.h>

#define BSZ  4
#define CH   128
#define HID  256
#define OUTD 64
#define EPSV 1e-5f
#define ALLM 0xffffffffu

// scratch for post-ReLU hidden activations: [5][4][256]
__device__ float g_r[5 * BSZ * HID];
// per-level monotone ticket counters (never reset; ticket math handles replays)
__device__ int g_cnt[5];

__device__ __forceinline__ int ld_acquire_gpu(const int* p)
{
    int v;
    asm volatile("ld.acquire.gpu.global.b32 %0, [%1];" : "=r"(v) : "l"(p) : "memory");
    return v;
}

__device__ __forceinline__ int atom_add_release(int* p, int v)
{
    int old;
    asm volatile("atom.add.release.gpu.global.s32 %0, [%1], %2;"
                 : "=r"(old) : "l"(p), "r"(v) : "memory");
    return old;
}

// ---------------------------------------------------------------------------
// Fused kernel: 40 blocks (k = bx>>3, chunk = bx&7), 256 threads.
// Gather issued FIRST (critical chain), weight prefetch hidden under it.
// Phase1: 32 hidden units -> g_r.  Ticket barrier.  Phase2: 8 outs x 4 b.
// ---------------------------------------------------------------------------
__global__ __launch_bounds__(256, 1)
void proj_fused_kernel(const float* __restrict__ x0,
                       const float* __restrict__ x1,
                       const float* __restrict__ x2,
                       const float* __restrict__ x3,
                       const float* __restrict__ x4,
                       const int*   __restrict__ p,
                       const float* __restrict__ w1,
                       const float* __restrict__ b1,
                       const float* __restrict__ gamma,
                       const float* __restrict__ beta,
                       const float* __restrict__ w2,
                       const float* __restrict__ b2,
                       float*       __restrict__ out)
{
    const int k   = blockIdx.x >> 3;       // level 0..4
    const int ch8 = blockIdx.x & 7;        // 32-unit chunk within level
    const int t   = threadIdx.x;
    const int s   = t & 7;                 // interleaved float4 slot
    const int j   = ch8 * 32 + (t >> 3);   // hidden unit (phase1)

    __shared__ float f_s[BSZ][CH];

    // ================= gather FIRST: the p -> x chain is the critical path ==
    const float* xs;
    switch (k) {
        case 0: xs = x0; break;
        case 1: xs = x1; break;
        case 2: xs = x2; break;
        case 3: xs = x3; break;
        default: xs = x4; break;
    }
    const int shift = k + 1;
    const int side  = 128 >> shift;

    {
        // two gather elements per thread: i and i+256
        const int i0 = t;
        const int i1 = t + 256;
        const int ba = i0 >> 7, ca = i0 & (CH - 1);
        const int bb = i1 >> 7, cb = i1 & (CH - 1);
        const int qa0 = p[ba * 3 + 0] >> shift;
        const int qa1 = p[ba * 3 + 1] >> shift;
        const int qa2 = p[ba * 3 + 2] >> shift;
        const int qb0 = p[bb * 3 + 0] >> shift;
        const int qb1 = p[bb * 3 + 1] >> shift;
        const int qb2 = p[bb * 3 + 2] >> shift;
        const long long ia =
            ((((long long)(ba * CH + ca) * side + qa0) * side + qa1) * side + qa2);
        const long long ib =
            ((((long long)(bb * CH + cb) * side + qb0) * side + qb1) * side + qb2);
        f_s[ba][ca] = xs[ia];
        f_s[bb][cb] = xs[ib];
    }

    // ---- weight / BN / w2 prefetch: latency hidden under gather ----
    const float4* wrow = (const float4*)(w1 + ((long long)k * HID + j) * CH);
    float4 wv[4];
    #pragma unroll
    for (int i = 0; i < 4; ++i)
        wv[i] = wrow[s + 8 * i];

    const float bias = b1[k * HID + j];
    const float gam  = gamma[k * HID + j];
    const float bet  = beta[k * HID + j];

    // phase2 assignment + w2 prefetch (independent of everything)
    const int T = t >> 3;                   // 0..31
    const int b = T & 3;
    const int o = ch8 * 8 + (T >> 2);
    const float4* w2row = (const float4*)(w2 + ((long long)k * OUTD + o) * HID);
    float4 wv2[8];
    #pragma unroll
    for (int i = 0; i < 8; ++i)
        wv2[i] = w2row[s + 8 * i];
    const float bias2 = b2[k * OUTD + o];

    __syncthreads();

    // ================= PHASE 1: 16 ch x 4 batches per thread =================
    const float4* f0 = (const float4*)f_s[0];
    const float4* f1 = (const float4*)f_s[1];
    const float4* f2 = (const float4*)f_s[2];
    const float4* f3 = (const float4*)f_s[3];

    float a0 = 0.f, a1 = 0.f, a2 = 0.f, a3 = 0.f;
    #pragma unroll
    for (int i = 0; i < 4; ++i) {
        const int fi = s + 8 * i;
        const float4 w = wv[i];
        float4 v;
        v = f0[fi]; a0 += v.x*w.x + v.y*w.y + v.z*w.z + v.w*w.w;
        v = f1[fi]; a1 += v.x*w.x + v.y*w.y + v.z*w.z + v.w*w.w;
        v = f2[fi]; a2 += v.x*w.x + v.y*w.y + v.z*w.z + v.w*w.w;
        v = f3[fi]; a3 += v.x*w.x + v.y*w.y + v.z*w.z + v.w*w.w;
    }
    #pragma unroll
    for (int m = 1; m < 8; m <<= 1) {
        a0 += __shfl_xor_sync(ALLM, a0, m);
        a1 += __shfl_xor_sync(ALLM, a1, m);
        a2 += __shfl_xor_sync(ALLM, a2, m);
        a3 += __shfl_xor_sync(ALLM, a3, m);
    }

    a0 += bias; a1 += bias; a2 += bias; a3 += bias;
    const float mean = 0.25f * (a0 + a1 + a2 + a3);
    const float d0 = a0 - mean, d1 = a1 - mean, d2 = a2 - mean, d3 = a3 - mean;
    const float var = 0.25f * (d0*d0 + d1*d1 + d2*d2 + d3*d3);
    const float scl = gam * rsqrtf(var + EPSV);

    if (s < 4) {
        const float d = (s == 0) ? d0 : (s == 1) ? d1 : (s == 2) ? d2 : d3;
        g_r[((long long)k * BSZ + s) * HID + j] = fmaxf(d * scl + bet, 0.f);
    }

    // ================= ticket barrier (one ATOMG, no reset) ==================
    __syncthreads();
    __shared__ int tgt_s;
    if (t == 0) {
        const int ticket = atom_add_release(&g_cnt[k], 1);   // releases g_r
        const int target = ((ticket >> 3) + 1) << 3;          // next multiple of 8
        while (ld_acquire_gpu(&g_cnt[k]) - target < 0) { }    // wrap-safe compare
        tgt_s = target;                                       // (also a dep sink)
    }
    __syncthreads();

    // ================= PHASE 2: 8 outs x 4 batches ===========================
    const float4* rrow = (const float4*)(g_r + ((long long)k * BSZ + b) * HID);
    float acc = 0.f;
    #pragma unroll
    for (int i = 0; i < 8; ++i) {
        const float4 w = wv2[i];
        const float4 r = rrow[s + 8 * i];
        acc += r.x*w.x + r.y*w.y + r.z*w.z + r.w*w.w;
    }
    #pragma unroll
    for (int m = 1; m < 8; m <<= 1)
        acc += __shfl_xor_sync(ALLM, acc, m);

    if (s == 0)
        out[((long long)k * BSZ + b) * OUTD + o] = acc + bias2;
}

extern "C" void kernel_launch(void* const* d_in, const int* in_sizes, int n_in,
                              void* d_out, int out_size)
{
    (void)in_sizes; (void)n_in; (void)out_size;
    const float* x0    = (const float*)d_in[0];
    const float* x1    = (const float*)d_in[1];
    const float* x2    = (const float*)d_in[2];
    const float* x3    = (const float*)d_in[3];
    const float* x4    = (const float*)d_in[4];
    const int*   p     = (const int*)  d_in[5];
    const float* w1    = (const float*)d_in[6];
    const float* b1    = (const float*)d_in[7];
    const float* gamma = (const float*)d_in[8];
    const float* beta  = (const float*)d_in[9];
    const float* w2    = (const float*)d_in[10];
    const float* b2v   = (const float*)d_in[11];
    float* out = (float*)d_out;

    proj_fused_kernel<<<40, 256>>>(x0, x1, x2, x3, x4, p,
                                   w1, b1, gamma, beta, w2, b2v, out);
}